// round 10
// baseline (speedup 1.0000x reference)
#include <cuda_runtime.h>
#include <math_constants.h>

// Statically-initialized accumulators; the last block resets them after use,
// so every graph replay sees zeros. No cudaMalloc, no extra launches.
__device__ double g_eme_sum = 0.0;
__device__ unsigned int g_eme_count = 0u;

// TWO adjacent 8x8 windows per thread: each thread reads a contiguous 64B
// (4 float4) per image row across 8 rows = 32 independent LDG.128 front-
// batched back-to-back (MLP_p1 = 32, fully-consumed cache lines).
// Input: (32,3,1024,1024) fp32 = 96 images of 1024x1024; 16384 windows/image.
// Grid: 6144 blocks x 128 threads x 2 windows = 1,572,864 windows exactly.
// min-blocks 3 with 128 threads -> 170-reg budget (32 float4 = 128 data regs).
__global__ __launch_bounds__(128, 3) void eme_fused_kernel(
    const float* __restrict__ y, float* __restrict__ out)
{
    const int t  = blockIdx.x * 128 + threadIdx.x;   // [0, 786432)
    const int w0 = t * 2;                             // first (even) window id

    const int img = w0 >> 14;          // 16384 windows per image
    const int rem = w0 & 16383;
    const int wy  = rem >> 7;          // window row 0..127
    const int wx  = rem & 127;         // window col (even)

    const float4* __restrict__ p = reinterpret_cast<const float4*>(
        y + (size_t)img * 1048576u + (size_t)wy * 8192u + (size_t)wx * 8u);
    // image row stride = 1024 floats = 256 float4

    // Load both windows: 8 rows x 4 contiguous float4 = 32 LDG.128.
    float4 v[32];
    #pragma unroll
    for (int r = 0; r < 8; r++) {
        #pragma unroll
        for (int c = 0; c < 4; c++)
            v[4 * r + c] = __ldcs(&p[r * 256 + c]);
    }

    // Window 0: columns c=0,1.  Window 1: columns c=2,3.
    float mx0 = -CUDART_INF_F, mn0 = CUDART_INF_F;
    float mx1 = -CUDART_INF_F, mn1 = CUDART_INF_F;
    #pragma unroll
    for (int r = 0; r < 8; r++) {
        #pragma unroll
        for (int c = 0; c < 2; c++) {
            const float4 a = v[4 * r + c];
            const float4 b = v[4 * r + 2 + c];
            mx0 = fmaxf(mx0, fmaxf(fmaxf(a.x, a.y), fmaxf(a.z, a.w)));
            mn0 = fminf(mn0, fminf(fminf(a.x, a.y), fminf(a.z, a.w)));
            mx1 = fmaxf(mx1, fmaxf(fmaxf(b.x, b.y), fmaxf(b.z, b.w)));
            mn1 = fminf(mn1, fminf(fminf(b.x, b.y), fminf(b.z, b.w)));
        }
    }

    float val = 0.0f;
    if (mx0 != mn0) val += 20.0f * logf(mx0 / (mn0 + 1e-4f));
    if (mx1 != mn1) val += 20.0f * logf(mx1 / (mn1 + 1e-4f));

    // Intra-warp reduction.
    #pragma unroll
    for (int o = 16; o > 0; o >>= 1)
        val += __shfl_xor_sync(0xffffffffu, val, o);

    __shared__ float warp_sums[4];
    const int lane = threadIdx.x & 31;
    const int wid  = threadIdx.x >> 5;
    if (lane == 0) warp_sums[wid] = val;
    __syncthreads();

    if (wid == 0) {
        float vv = (lane < 4) ? warp_sums[lane] : 0.0f;
        #pragma unroll
        for (int o = 2; o > 0; o >>= 1)
            vv += __shfl_xor_sync(0xffffffffu, vv, o);

        if (lane == 0) {
            atomicAdd(&g_eme_sum, (double)vv);
            __threadfence();
            unsigned int done = atomicAdd(&g_eme_count, 1u);
            if (done == gridDim.x - 1u) {
                // All partials visible (each block fenced before incrementing).
                double s = g_eme_sum;
                // result = sum / (B * row * col / (w*w)) = sum / 524288
                out[0] = (float)(s * (1.0 / 524288.0));
                // Reset for the next graph replay.
                g_eme_sum = 0.0;
                g_eme_count = 0u;
            }
        }
    }
}

extern "C" void kernel_launch(void* const* d_in, const int* in_sizes, int n_in,
                              void* d_out, int out_size)
{
    const float* y = (const float*)d_in[0];
    float* out = (float*)d_out;

    const int n_windows = 32 * 3 * 128 * 128;   // 1,572,864
    const int threads = 128;
    const int blocks = n_windows / (threads * 2);  // 6144, exact

    eme_fused_kernel<<<blocks, threads>>>(y, out);
}

// round 11
// speedup vs baseline: 1.0377x; 1.0377x over previous
#include <cuda_runtime.h>
#include <math_constants.h>

// Statically-initialized accumulators; the last block resets them after use,
// so every graph replay sees zeros. No cudaMalloc, no extra launches.
__device__ double g_eme_sum = 0.0;
__device__ unsigned int g_eme_count = 0u;

// One thread per 8x8 window. Input logical shape (32,3,1024,1024) fp32,
// treated as 96 images of 1024x1024. Windows per image: 128x128.
// Grid: 6144 blocks x 256 threads = 1,572,864 windows exactly.
// min-blocks 3 -> 85-reg budget: front-batch ALL 16 LDG.128 of the window
// (64 data regs), MLP_p1 = 16 — the measured optimum of the MLP sweep
// (4: 62.2us, 8: 62.0us, 16: 61.5us, 32: 64.2us). Kernel is pinned at the
// chip's streaming-read ceiling (~6.4 TB/s sustained, DRAM ~81%); occupancy
// 29%-85% and access-layout variants all measure within 1%.
__global__ __launch_bounds__(256, 3) void eme_fused_kernel(
    const float* __restrict__ y, float* __restrict__ out)
{
    const int w = blockIdx.x * 256 + threadIdx.x;

    const int img = w >> 14;          // 16384 windows per image
    const int rem = w & 16383;
    const int wy  = rem >> 7;         // window row 0..127
    const int wx  = rem & 127;        // window col 0..127

    const float4* __restrict__ p = reinterpret_cast<const float4*>(
        y + (size_t)img * 1048576u + (size_t)wy * 8192u + (size_t)wx * 8u);
    // image row stride = 1024 floats = 256 float4

    // Load the whole 8x8 window: 16 independent LDG.128 back-to-back.
    float4 v[16];
    #pragma unroll
    for (int r = 0; r < 8; r++) {
        v[2 * r]     = __ldcs(&p[r * 256]);
        v[2 * r + 1] = __ldcs(&p[r * 256 + 1]);
    }

    float mx = -CUDART_INF_F;
    float mn =  CUDART_INF_F;
    #pragma unroll
    for (int i = 0; i < 16; i++) {
        mx = fmaxf(mx, fmaxf(fmaxf(v[i].x, v[i].y), fmaxf(v[i].z, v[i].w)));
        mn = fminf(mn, fminf(fminf(v[i].x, v[i].y), fminf(v[i].z, v[i].w)));
    }

    float val = 0.0f;
    if (mx != mn) {
        val = 20.0f * logf(mx / (mn + 1e-4f));
    }

    // Intra-warp reduction.
    #pragma unroll
    for (int o = 16; o > 0; o >>= 1)
        val += __shfl_xor_sync(0xffffffffu, val, o);

    __shared__ float warp_sums[8];
    const int lane = threadIdx.x & 31;
    const int wid  = threadIdx.x >> 5;
    if (lane == 0) warp_sums[wid] = val;
    __syncthreads();

    if (wid == 0) {
        float vv = (lane < 8) ? warp_sums[lane] : 0.0f;
        #pragma unroll
        for (int o = 4; o > 0; o >>= 1)
            vv += __shfl_xor_sync(0xffffffffu, vv, o);

        if (lane == 0) {
            atomicAdd(&g_eme_sum, (double)vv);
            __threadfence();
            unsigned int done = atomicAdd(&g_eme_count, 1u);
            if (done == gridDim.x - 1u) {
                // All partials visible (each block fenced before incrementing).
                double s = g_eme_sum;
                // result = sum / (B * row * col / (w*w)) = sum / 524288
                out[0] = (float)(s * (1.0 / 524288.0));
                // Reset for the next graph replay.
                g_eme_sum = 0.0;
                g_eme_count = 0u;
            }
        }
    }
}

extern "C" void kernel_launch(void* const* d_in, const int* in_sizes, int n_in,
                              void* d_out, int out_size)
{
    const float* y = (const float*)d_in[0];
    float* out = (float*)d_out;

    const int n_windows = 32 * 3 * 128 * 128;  // 1,572,864
    const int threads = 256;
    const int blocks = n_windows / threads;    // 6144, exact

    eme_fused_kernel<<<blocks, threads>>>(y, out);
}